// round 16
// baseline (speedup 1.0000x reference)
#include <cuda_runtime.h>
#include <cuda_bf16.h>
#include <mma.h>
#include <math.h>
#include <stdint.h>

using namespace nvcuda;

// Problem constants
#define DDIM 1024
#define NEXP 8
#define HDIM 4096
#define TOPK 2
#define NTOK 8192               // B*S
#define NROWS (NTOK * TOPK)     // 16384

// WMMA fast-path tile: 128(M) x 128(N) x 16(K), 4-stage pipeline, 8 warps (64x32)
#define TM 128
#define TN 128
#define KC 16
#define NSTG 4
#define A_PAD 24                // A smem k-stride (elems) -> 48B rows (conflict-free LDSM)
#define B_PAD 136               // B smem n-stride (elems) -> 272B rows (conflict-free)
#define A_ELS (128 * A_PAD)     // 3072 elems per (hi|lo) buffer
#define B_ELS (KC * B_PAD)      // 2176 elems
#define STG_ELS (2 * A_ELS + 2 * B_ELS)   // 10496 elems = 20992 B per stage
#define SMEM_DYN (NSTG * STG_ELS * 2)     // 83968 B; 2 CTAs/SM = 167936 B < 228KB

// Fallback tile
#define FBM 128
#define FBN 128
#define FBK 16

// ---------------- scratch (device globals; ONLY referenced in-body, NEVER as args)
__device__ __nv_bfloat16 g_xhi[(size_t)NTOK * DDIM];
__device__ __nv_bfloat16 g_xlo[(size_t)NTOK * DDIM];
__device__ __nv_bfloat16 g_w1hi[(size_t)NEXP * DDIM * HDIM];   // [E][K=D][N=H]
__device__ __nv_bfloat16 g_w1lo[(size_t)NEXP * DDIM * HDIM];
__device__ __nv_bfloat16 g_w2hi[(size_t)NEXP * HDIM * DDIM];   // [E][K=H][N=D]
__device__ __nv_bfloat16 g_w2lo[(size_t)NEXP * HDIM * DDIM];
__device__ __nv_bfloat16 g_hhi[(size_t)NROWS * HDIM];
__device__ __nv_bfloat16 g_hlo[(size_t)NROWS * HDIM];
__device__ float g_oscr[(size_t)NROWS * DDIM];
__device__ int   g_rows_token[NROWS];
__device__ int   g_rows_dest[NROWS];
__device__ float g_wslot[NROWS];
__device__ int   g_tok_eidx[NROWS];
__device__ int   g_counts[NEXP];
__device__ int   g_offsets[NEXP + 1];
__device__ int   g_fill[NEXP];
__device__ int   g_flag1;
__device__ int   g_flag2;
__device__ int   g_nan1;
__device__ int   g_nan2;

// ---------------- helpers ------------------------------------------------------
__device__ __forceinline__ uint32_t smem_u32(const void* p) {
    return (uint32_t)__cvta_generic_to_shared(p);
}
__device__ __forceinline__ void cpasync16(uint32_t s, const void* g) {
    asm volatile("cp.async.cg.shared.global [%0], [%1], 16;" :: "r"(s), "l"(g));
}
__device__ __forceinline__ void cp_commit() {
    asm volatile("cp.async.commit_group;" ::: "memory");
}
__device__ __forceinline__ void cp_wait2() {
    asm volatile("cp.async.wait_group 2;" ::: "memory");
}
__device__ __forceinline__ void cp_wait1() {
    asm volatile("cp.async.wait_group 1;" ::: "memory");
}
__device__ __forceinline__ void cp_wait0() {
    asm volatile("cp.async.wait_group 0;" ::: "memory");
}
__device__ __forceinline__ float gelu_exact(float v) {
    return 0.5f * v * (1.0f + erff(v * 0.70710678118654752440f));
}
__device__ __forceinline__ void split2(float v0, float v1,
                                       __nv_bfloat162& h2, __nv_bfloat162& l2) {
    __nv_bfloat16 h0 = __float2bfloat16(v0);
    __nv_bfloat16 h1 = __float2bfloat16(v1);
    __nv_bfloat16 l0 = __float2bfloat16(v0 - __bfloat162float(h0));
    __nv_bfloat16 l1 = __float2bfloat16(v1 - __bfloat162float(h1));
    h2 = __nv_bfloat162(h0, h1);
    l2 = __nv_bfloat162(l0, l1);
}
__device__ __forceinline__ float bf_lo(uint32_t u) {
    return __bfloat162float(__ushort_as_bfloat16((unsigned short)(u & 0xFFFF)));
}
__device__ __forceinline__ float bf_hi(uint32_t u) {
    return __bfloat162float(__ushort_as_bfloat16((unsigned short)(u >> 16)));
}

// ---------------- gating (proven) -----------------------------------------------
__global__ void reset_kernel() {
    int i = threadIdx.x;
    if (i < NEXP) g_counts[i] = 0;
    if (i == 0) { g_flag1 = 1; g_flag2 = 1; g_nan1 = 0; g_nan2 = 0; }
}

__global__ void gate_kernel(const float* __restrict__ x, const float* __restrict__ gw) {
    int warp = (blockIdx.x * blockDim.x + threadIdx.x) >> 5;
    int lane = threadIdx.x & 31;
    if (warp >= NTOK) return;
    const float* xr = x + (size_t)warp * DDIM;

    float acc[NEXP];
#pragma unroll
    for (int e = 0; e < NEXP; e++) acc[e] = 0.f;
    for (int d = lane; d < DDIM; d += 32) {
        float xv = xr[d];
        const float* g = gw + (size_t)d * NEXP;
#pragma unroll
        for (int e = 0; e < NEXP; e++) acc[e] = fmaf(xv, g[e], acc[e]);
    }
#pragma unroll
    for (int e = 0; e < NEXP; e++) {
#pragma unroll
        for (int o = 16; o > 0; o >>= 1)
            acc[e] += __shfl_xor_sync(0xffffffff, acc[e], o);
    }
    if (lane == 0) {
        int b0 = 0; float s0 = acc[0];
#pragma unroll
        for (int e = 1; e < NEXP; e++) if (acc[e] > s0) { s0 = acc[e]; b0 = e; }
        int b1 = -1; float s1 = -INFINITY;
#pragma unroll
        for (int e = 0; e < NEXP; e++)
            if (e != b0 && acc[e] > s1) { s1 = acc[e]; b1 = e; }
        float p = expf(s1 - s0);
        float inv = 1.0f / (1.0f + p);
        g_tok_eidx[warp * 2 + 0] = b0;
        g_tok_eidx[warp * 2 + 1] = b1;
        g_wslot[warp * 2 + 0] = inv;
        g_wslot[warp * 2 + 1] = p * inv;
        atomicAdd(&g_counts[b0], 1);
        atomicAdd(&g_counts[b1], 1);
    }
}

__global__ void scan_kernel() {
    int s = 0;
    for (int e = 0; e < NEXP; e++) {
        g_offsets[e] = s;
        s += g_counts[e];
        g_fill[e] = 0;
    }
    g_offsets[NEXP] = s;
}

__global__ void build_kernel() {
    int t = blockIdx.x * blockDim.x + threadIdx.x;
    if (t >= NTOK) return;
#pragma unroll
    for (int k = 0; k < TOPK; k++) {
        int e = g_tok_eidx[t * 2 + k];
        int pos = g_offsets[e] + atomicAdd(&g_fill[e], 1);
        g_rows_token[pos] = t;
        g_rows_dest[pos] = t * 2 + k;
    }
}

// ---------------- fp32 -> bf16 hi/lo split; dest selected IN-BODY ---------------
template <int W>
__global__ void split_kernel(const float* __restrict__ src) {
    __nv_bfloat16* dhi = (W == 0) ? g_xhi : (W == 1) ? g_w1hi : g_w2hi;
    __nv_bfloat16* dlo = (W == 0) ? g_xlo : (W == 1) ? g_w1lo : g_w2lo;
    size_t i = (size_t)blockIdx.x * blockDim.x + threadIdx.x;   // 4 elems each
    float4 v = reinterpret_cast<const float4*>(src)[i];
    __nv_bfloat162 h0, l0, h1, l1;
    split2(v.x, v.y, h0, l0);
    split2(v.z, v.w, h1, l1);
    reinterpret_cast<__nv_bfloat162*>(dhi)[2 * i]     = h0;
    reinterpret_cast<__nv_bfloat162*>(dhi)[2 * i + 1] = h1;
    reinterpret_cast<__nv_bfloat162*>(dlo)[2 * i]     = l0;
    reinterpret_cast<__nv_bfloat162*>(dlo)[2 * i + 1] = l1;
}

// ---------------- FAST grouped GEMM: 4-stage, 1 barrier/chunk, EARLY load issue ---
// MODE 1: A = x hi/lo (gathered), B = w1 hi/lo [K=D][N=H], +b1, GELU -> g_h hi/lo
// MODE 2: A = g_h hi/lo (contig), B = w2 hi/lo [K=H][N=D], +b2 -> g_oscr[slot]
template <int MODE>
__global__ __launch_bounds__(256, 2)
void moe_gemm_wmma(const float* __restrict__ bias) {
    constexpr int KDIM = (MODE == 1) ? DDIM : HDIM;
    constexpr int NDIM = (MODE == 1) ? HDIM : DDIM;
    constexpr int NCH = KDIM / KC;

    extern __shared__ __align__(16) __nv_bfloat16 sm[];

    // proven grid mapping: z = expert, y = m-tile, x = n-tile
    int e = blockIdx.z;
    int roff = g_offsets[e];
    int cnt = g_offsets[e + 1] - roff;
    int m0 = blockIdx.y * TM;
    if (m0 >= cnt) return;
    int n0 = blockIdx.x * TN;

    int tid = threadIdx.x;
    int wid = tid >> 5, lane = tid & 31;
    int wm = wid & 1;            // m block: wm*64 (4 frags)
    int wn = wid >> 1;           // n block: wn*32 (2 frags)

    const __nv_bfloat16* Ahi = (MODE == 1) ? g_xhi : g_hhi;
    const __nv_bfloat16* Alo = (MODE == 1) ? g_xlo : g_hlo;
    const __nv_bfloat16* Bhi = ((MODE == 1) ? g_w1hi : g_w2hi) + (size_t)e * KDIM * NDIM;
    const __nv_bfloat16* Blo = ((MODE == 1) ? g_w1lo : g_w2lo) + (size_t)e * KDIM * NDIM;

    // --- cp.async staging geometry -----------------------------------------------
    int arow = tid >> 1;
    int akc = (tid & 1) * 8;
    int src;
    if (MODE == 1) {
        src = (m0 + arow < cnt) ? g_rows_token[roff + m0 + arow] : 0;
    } else {
        int g = roff + m0 + arow;
        src = (g < NROWS) ? g : (NROWS - 1);
    }
    size_t aofs = (size_t)src * KDIM + akc;
    uint32_t a_dst = (uint32_t)(arow * A_PAD + akc) * 2;
    int bkr = tid >> 4;
    int bnc = (tid & 15) * 8;
    size_t bofs = (size_t)bkr * NDIM + n0 + bnc;
    uint32_t b_dst = (uint32_t)(bkr * B_PAD + bnc) * 2;

    uint32_t smb = smem_u32(sm);

    auto load_stage = [&](int c) {
        uint32_t sb = smb + (uint32_t)(c % NSTG) * (STG_ELS * 2);
        size_t k0 = (size_t)c * KC;
        cpasync16(sb + a_dst,                           Ahi + aofs + k0);
        cpasync16(sb + A_ELS * 2 + a_dst,               Alo + aofs + k0);
        cpasync16(sb + 2 * A_ELS * 2 + b_dst,           Bhi + bofs + k0 * NDIM);
        cpasync16(sb + (2 * A_ELS + B_ELS) * 2 + b_dst, Blo + bofs + k0 * NDIM);
        cp_commit();
    };

    wmma::fragment<wmma::accumulator, 16, 16, 16, float> acc[4][2];
#pragma unroll
    for (int mf = 0; mf < 4; mf++)
#pragma unroll
        for (int nf = 0; nf < 2; nf++)
            wmma::fill_fragment(acc[mf][nf], 0.0f);

    // prologue: NSTG-1 stages in flight
    load_stage(0);
    load_stage(1);
    load_stage(2);

    for (int c = 0; c < NCH; c++) {
        // wait for stage c (own groups), THEN make visible block-wide.
        int rem = NCH - 1 - c;
        if (rem >= 2) cp_wait2();
        else if (rem == 1) cp_wait1();
        else cp_wait0();
        __syncthreads();   // visibility of stage c + WAR retire of compute(c-1)

        // EARLY ISSUE (R16): next load fired before compute, maximizing memory lead.
        // Writes buffer (c+3)%4 == (c-1)%4; its readers (compute c-1) all passed
        // the barrier above. This chunk reads buffer c%4 — disjoint. Safe.
        if (c + 3 < NCH) load_stage(c + 3);

        const __nv_bfloat16* base = sm + (c % NSTG) * STG_ELS;
        const __nv_bfloat16* pAh = base;
        const __nv_bfloat16* pAl = base + A_ELS;
        const __nv_bfloat16* pBh = base + 2 * A_ELS;
        const __nv_bfloat16* pBl = base + 2 * A_ELS + B_ELS;

        wmma::fragment<wmma::matrix_b, 16, 16, 16, __nv_bfloat16, wmma::row_major> bH[2], bL[2];
#pragma unroll
        for (int nf = 0; nf < 2; nf++) {
            wmma::load_matrix_sync(bH[nf], pBh + wn * 32 + nf * 16, B_PAD);
            wmma::load_matrix_sync(bL[nf], pBl + wn * 32 + nf * 16, B_PAD);
        }
#pragma unroll
        for (int mf = 0; mf < 4; mf++) {
            wmma::fragment<wmma::matrix_a, 16, 16, 16, __nv_bfloat16, wmma::row_major> aH, aL;
            const __nv_bfloat16* aa = pAh + (wm * 64 + mf * 16) * A_PAD;
            wmma::load_matrix_sync(aH, aa, A_PAD);
            wmma::load_matrix_sync(aL, aa + A_ELS, A_PAD);
#pragma unroll
            for (int nf = 0; nf < 2; nf++) {
                wmma::mma_sync(acc[mf][nf], aH, bH[nf], acc[mf][nf]);
                wmma::mma_sync(acc[mf][nf], aH, bL[nf], acc[mf][nf]);
                wmma::mma_sync(acc[mf][nf], aL, bH[nf], acc[mf][nf]);
            }
        }
    }

    // --- epilogue: per-warp smem scratch ------------------------------------------
    __syncthreads();
    float* scr = reinterpret_cast<float*>(sm) + wid * 16 * 20;   // 16x16 tile, ldm=20
    const float* be = bias + (size_t)e * NDIM;
    int lrow = lane >> 1;
    int lcol = (lane & 1) * 8;
#pragma unroll
    for (int mf = 0; mf < 4; mf++) {
#pragma unroll
        for (int nf = 0; nf < 2; nf++) {
            wmma::store_matrix_sync(scr, acc[mf][nf], 20, wmma::mem_row_major);
            __syncwarp();
            int r = m0 + wm * 64 + mf * 16 + lrow;
            if (r < cnt) {
                int col = n0 + wn * 32 + nf * 16 + lcol;
                if (MODE == 1) {
                    size_t drow = (size_t)(roff + r) * NDIM;
#pragma unroll
                    for (int j = 0; j < 8; j += 2) {
                        float v0 = gelu_exact(scr[lrow * 20 + lcol + j]     + be[col + j]);
                        float v1 = gelu_exact(scr[lrow * 20 + lcol + j + 1] + be[col + j + 1]);
                        __nv_bfloat162 h2, l2;
                        split2(v0, v1, h2, l2);
                        *reinterpret_cast<__nv_bfloat162*>(g_hhi + drow + col + j) = h2;
                        *reinterpret_cast<__nv_bfloat162*>(g_hlo + drow + col + j) = l2;
                    }
                } else {
                    size_t drow = (size_t)g_rows_dest[roff + r] * NDIM;
                    float out[8];
#pragma unroll
                    for (int j = 0; j < 8; j++)
                        out[j] = scr[lrow * 20 + lcol + j] + be[col + j];
                    float* dst = g_oscr + drow + col;
                    *reinterpret_cast<float4*>(dst)     = make_float4(out[0], out[1], out[2], out[3]);
                    *reinterpret_cast<float4*>(dst + 4) = make_float4(out[4], out[5], out[6], out[7]);
                }
            }
            __syncwarp();
        }
    }
}

// ---------------- check kernels: dead (all-zero) AND NaN detection ----------------
__global__ void check_h_kernel() {
    size_t idx = ((size_t)blockIdx.x * blockDim.x + threadIdx.x) * 1024;
    if (idx < (size_t)NROWS * HDIM) {
        unsigned short u = __bfloat16_as_ushort(g_hhi[idx]);
        if (u != 0) g_flag1 = 0;
        if ((u & 0x7F80) == 0x7F80 && (u & 0x007F) != 0) g_nan1 = 1;   // bf16 NaN
    }
}
__global__ void check_o_kernel() {
    size_t idx = ((size_t)blockIdx.x * blockDim.x + threadIdx.x) * 1024;
    if (idx < (size_t)NROWS * DDIM) {
        float v = g_oscr[idx];
        if (v != 0.0f) g_flag2 = 0;
        if (isnan(v) || isinf(v)) g_nan2 = 1;
    }
}

// ---------------- FALLBACK SIMT GEMMs (proven; statics in-body) ------------------
template <int MODE>
__global__ __launch_bounds__(256)
void fb_gemm(const float* __restrict__ Aparam,
             const float* __restrict__ Bmat,
             const float* __restrict__ bias) {
    if (MODE == 1) { if (g_flag1 == 0 && g_nan1 == 0) return; }
    else           { if (g_flag2 == 0 && g_nan2 == 0) return; }

    constexpr int KDIM = (MODE == 1) ? DDIM : HDIM;
    constexpr int NDIM = (MODE == 1) ? HDIM : DDIM;

    int e = blockIdx.z;
    int roff = g_offsets[e];
    int cnt = g_offsets[e + 1] - roff;
    int m0 = blockIdx.y * FBM;
    if (m0 >= cnt) return;
    int n0 = blockIdx.x * FBN;

    const float* Bexp = Bmat + (size_t)e * KDIM * NDIM;
    const float* bexp = bias + (size_t)e * NDIM;

    __shared__ float As[FBK][FBM];
    __shared__ float Bs[FBK][FBN];
    __shared__ int rowsrc[FBM];

    int tid = threadIdx.x;
    if (tid < FBM) {
        int r = m0 + tid;
        int src = -1;
        if (r < cnt) src = (MODE == 1) ? g_rows_token[roff + r] : (roff + r);
        rowsrc[tid] = src;
    }
    __syncthreads();

    float acc[8][8];
#pragma unroll
    for (int i = 0; i < 8; i++)
#pragma unroll
        for (int j = 0; j < 8; j++) acc[i][j] = 0.f;

    int ty = tid >> 4, tx = tid & 15;

    for (int k0 = 0; k0 < KDIM; k0 += FBK) {
#pragma unroll
        for (int p = 0; p < 2; p++) {
            int row = (tid >> 2) + p * 64;
            int c4 = (tid & 3) * 4;
            int src = rowsrc[row];
            float f0 = 0.f, f1 = 0.f, f2 = 0.f, f3 = 0.f;
            if (src >= 0) {
                if (MODE == 1) {
                    float4 v = *reinterpret_cast<const float4*>(
                        Aparam + (size_t)src * KDIM + k0 + c4);
                    f0 = v.x; f1 = v.y; f2 = v.z; f3 = v.w;
                } else {
                    uint2 vh = *reinterpret_cast<const uint2*>(g_hhi + (size_t)src * KDIM + k0 + c4);
                    uint2 vl = *reinterpret_cast<const uint2*>(g_hlo + (size_t)src * KDIM + k0 + c4);
                    f0 = bf_lo(vh.x) + bf_lo(vl.x);
                    f1 = bf_hi(vh.x) + bf_hi(vl.x);
                    f2 = bf_lo(vh.y) + bf_lo(vl.y);
                    f3 = bf_hi(vh.y) + bf_hi(vl.y);
                }
            }
            As[c4 + 0][row] = f0;
            As[c4 + 1][row] = f1;
            As[c4 + 2][row] = f2;
            As[c4 + 3][row] = f3;
        }
#pragma unroll
        for (int p = 0; p < 2; p++) {
            int brow2 = (tid >> 5) + p * 8;
            int bc = (tid & 31) * 4;
            float4 v = *reinterpret_cast<const float4*>(
                Bexp + (size_t)(k0 + brow2) * NDIM + n0 + bc);
            *reinterpret_cast<float4*>(&Bs[brow2][bc]) = v;
        }
        __syncthreads();

#pragma unroll
        for (int kk = 0; kk < FBK; kk++) {
            float a[8], b[8];
#pragma unroll
            for (int i = 0; i < 8; i++) a[i] = As[kk][ty * 8 + i];
#pragma unroll
            for (int j = 0; j < 8; j++) b[j] = Bs[kk][tx * 8 + j];
#pragma unroll
            for (int i = 0; i < 8; i++)
#pragma unroll
                for (int j = 0; j < 8; j++)
                    acc[i][j] = fmaf(a[i], b[j], acc[i][j]);
        }
        __syncthreads();
    }

#pragma unroll
    for (int i = 0; i < 8; i++) {
        int r = m0 + ty * 8 + i;
        if (r >= cnt) continue;
#pragma unroll
        for (int j = 0; j < 8; j++) {
            int col = n0 + tx * 8 + j;
            float v = acc[i][j] + bexp[col];
            if (MODE == 1) {
                v = gelu_exact(v);
                __nv_bfloat16 h = __float2bfloat16(v);
                __nv_bfloat16 l = __float2bfloat16(v - __bfloat162float(h));
                size_t o = (size_t)(roff + r) * NDIM + col;
                g_hhi[o] = h;
                g_hlo[o] = l;
            } else {
                int slot = g_rows_dest[roff + r];
                g_oscr[(size_t)slot * NDIM + col] = v;
            }
        }
    }
}

// ---------------- combine ------------------------------------------------------
__global__ void combine_kernel(float* __restrict__ y) {
    int idx = blockIdx.x * blockDim.x + threadIdx.x;
    if (idx >= NTOK * DDIM) return;
    int t = idx >> 10;
    int d = idx & (DDIM - 1);
    float w0 = g_wslot[t * 2 + 0];
    float w1 = g_wslot[t * 2 + 1];
    float v0 = g_oscr[(size_t)(t * 2 + 0) * DDIM + d];
    float v1 = g_oscr[(size_t)(t * 2 + 1) * DDIM + d];
    y[idx] = fmaf(w0, v0, w1 * v1);
}

// ---------------- launch (NO device symbols passed as kernel arguments) ---------
extern "C" void kernel_launch(void* const* d_in, const int* in_sizes, int n_in,
                              void* d_out, int out_size) {
    const float* x  = (const float*)d_in[0];  // [B,S,D]
    const float* gw = (const float*)d_in[1];  // [D,E]
    const float* w1 = (const float*)d_in[2];  // [E,D,H]
    const float* b1 = (const float*)d_in[3];  // [E,H]
    const float* w2 = (const float*)d_in[4];  // [E,H,D]
    const float* b2 = (const float*)d_in[5];  // [E,D]
    float* y = (float*)d_out;

    // dynamic smem opt-in (host attribute; capture-safe, proven)
    cudaFuncSetAttribute(moe_gemm_wmma<1>, cudaFuncAttributeMaxDynamicSharedMemorySize, SMEM_DYN);
    cudaFuncSetAttribute(moe_gemm_wmma<2>, cudaFuncAttributeMaxDynamicSharedMemorySize, SMEM_DYN);

    reset_kernel<<<1, 32>>>();
    gate_kernel<<<NTOK / 8, 256>>>(x, gw);
    scan_kernel<<<1, 1>>>();
    build_kernel<<<NTOK / 256, 256>>>();

    // convert-once hi/lo splits (dest statics selected in-body)
    split_kernel<0><<<(NTOK * DDIM / 4) / 256, 256>>>(x);
    split_kernel<1><<<((size_t)NEXP * DDIM * HDIM / 4) / 256, 256>>>(w1);
    split_kernel<2><<<((size_t)NEXP * HDIM * DDIM / 4) / 256, 256>>>(w2);

    // fast GEMM1 (wmma) + self-check + fallback
    moe_gemm_wmma<1><<<dim3(HDIM / TN, NROWS / TM, NEXP), 256, SMEM_DYN>>>(b1);
    check_h_kernel<<<256, 256>>>();
    fb_gemm<1><<<dim3(HDIM / FBN, NROWS / FBM, NEXP), 256>>>(x, w1, b1);

    // fast GEMM2 + self-check + fallback
    moe_gemm_wmma<2><<<dim3(DDIM / TN, NROWS / TM, NEXP), 256, SMEM_DYN>>>(b2);
    check_o_kernel<<<64, 256>>>();
    fb_gemm<2><<<dim3(DDIM / FBN, NROWS / FBM, NEXP), 256>>>(nullptr, w2, b2);

    combine_kernel<<<(NTOK * DDIM) / 256, 256>>>(y);
}

// round 17
// speedup vs baseline: 1.7669x; 1.7669x over previous
#include <cuda_runtime.h>
#include <cuda_fp16.h>
#include <mma.h>
#include <math.h>
#include <stdint.h>

using namespace nvcuda;

// Problem constants
#define DDIM 1024
#define NEXP 8
#define HDIM 4096
#define TOPK 2
#define NTOK 8192               // B*S
#define NROWS (NTOK * TOPK)     // 16384

// WMMA fast-path tile: 128(M) x 128(N) x 16(K), 4-stage pipeline, 8 warps (64x32)
// fp16 2-pass: A split hi/lo (22-bit effective), B rounded once (11-bit).
#define TM 128
#define TN 128
#define KC 16
#define NSTG 4
#define A_PAD 24                // A smem k-stride (elems) -> 48B rows
#define B_PAD 136               // B smem n-stride (elems) -> 272B rows
#define A_ELS (128 * A_PAD)     // 3072 elems per (hi|lo) buffer
#define B_ELS (KC * B_PAD)      // 2176 elems (hi only)
#define STG_ELS (2 * A_ELS + B_ELS)       // 8320 elems = 16640 B per stage
#define SMEM_DYN (NSTG * STG_ELS * 2)     // 66560 B; 2 CTAs/SM = 133120 B < 228KB

// Fallback tile
#define FBM 128
#define FBN 128
#define FBK 16

// ---------------- scratch (device globals; ONLY referenced in-body, NEVER as args)
__device__ __half g_xhi[(size_t)NTOK * DDIM];
__device__ __half g_xlo[(size_t)NTOK * DDIM];
__device__ __half g_w1h[(size_t)NEXP * DDIM * HDIM];   // [E][K=D][N=H], hi only
__device__ __half g_w2h[(size_t)NEXP * HDIM * DDIM];   // [E][K=H][N=D], hi only
__device__ __half g_hhi[(size_t)NROWS * HDIM];
__device__ __half g_hlo[(size_t)NROWS * HDIM];
__device__ float g_oscr[(size_t)NROWS * DDIM];
__device__ int   g_rows_token[NROWS];
__device__ int   g_rows_dest[NROWS];
__device__ float g_wslot[NROWS];
__device__ int   g_tok_eidx[NROWS];
__device__ int   g_counts[NEXP];
__device__ int   g_offsets[NEXP + 1];
__device__ int   g_fill[NEXP];
__device__ int   g_flag1;
__device__ int   g_flag2;
__device__ int   g_nan1;
__device__ int   g_nan2;

// ---------------- helpers ------------------------------------------------------
__device__ __forceinline__ uint32_t smem_u32(const void* p) {
    return (uint32_t)__cvta_generic_to_shared(p);
}
__device__ __forceinline__ void cpasync16(uint32_t s, const void* g) {
    asm volatile("cp.async.cg.shared.global [%0], [%1], 16;" :: "r"(s), "l"(g));
}
__device__ __forceinline__ void cp_commit() {
    asm volatile("cp.async.commit_group;" ::: "memory");
}
__device__ __forceinline__ void cp_wait2() {
    asm volatile("cp.async.wait_group 2;" ::: "memory");
}
__device__ __forceinline__ void cp_wait1() {
    asm volatile("cp.async.wait_group 1;" ::: "memory");
}
__device__ __forceinline__ void cp_wait0() {
    asm volatile("cp.async.wait_group 0;" ::: "memory");
}
__device__ __forceinline__ float gelu_exact(float v) {
    return 0.5f * v * (1.0f + erff(v * 0.70710678118654752440f));
}
// fp16 hi/lo split (hi = round(v), lo = round(v - hi)); ~22-bit effective mantissa
__device__ __forceinline__ void split2h(float v0, float v1, __half2& h2, __half2& l2) {
    __half h0 = __float2half(v0);
    __half h1 = __float2half(v1);
    __half l0 = __float2half(v0 - __half2float(h0));
    __half l1 = __float2half(v1 - __half2float(h1));
    h2 = __halves2half2(h0, h1);
    l2 = __halves2half2(l0, l1);
}

// ---------------- gating (proven) -----------------------------------------------
__global__ void reset_kernel() {
    int i = threadIdx.x;
    if (i < NEXP) g_counts[i] = 0;
    if (i == 0) { g_flag1 = 1; g_flag2 = 1; g_nan1 = 0; g_nan2 = 0; }
}

__global__ void gate_kernel(const float* __restrict__ x, const float* __restrict__ gw) {
    int warp = (blockIdx.x * blockDim.x + threadIdx.x) >> 5;
    int lane = threadIdx.x & 31;
    if (warp >= NTOK) return;
    const float* xr = x + (size_t)warp * DDIM;

    float acc[NEXP];
#pragma unroll
    for (int e = 0; e < NEXP; e++) acc[e] = 0.f;
    for (int d = lane; d < DDIM; d += 32) {
        float xv = xr[d];
        const float* g = gw + (size_t)d * NEXP;
#pragma unroll
        for (int e = 0; e < NEXP; e++) acc[e] = fmaf(xv, g[e], acc[e]);
    }
#pragma unroll
    for (int e = 0; e < NEXP; e++) {
#pragma unroll
        for (int o = 16; o > 0; o >>= 1)
            acc[e] += __shfl_xor_sync(0xffffffff, acc[e], o);
    }
    if (lane == 0) {
        int b0 = 0; float s0 = acc[0];
#pragma unroll
        for (int e = 1; e < NEXP; e++) if (acc[e] > s0) { s0 = acc[e]; b0 = e; }
        int b1 = -1; float s1 = -INFINITY;
#pragma unroll
        for (int e = 0; e < NEXP; e++)
            if (e != b0 && acc[e] > s1) { s1 = acc[e]; b1 = e; }
        float p = expf(s1 - s0);
        float inv = 1.0f / (1.0f + p);
        g_tok_eidx[warp * 2 + 0] = b0;
        g_tok_eidx[warp * 2 + 1] = b1;
        g_wslot[warp * 2 + 0] = inv;
        g_wslot[warp * 2 + 1] = p * inv;
        atomicAdd(&g_counts[b0], 1);
        atomicAdd(&g_counts[b1], 1);
    }
}

__global__ void scan_kernel() {
    int s = 0;
    for (int e = 0; e < NEXP; e++) {
        g_offsets[e] = s;
        s += g_counts[e];
        g_fill[e] = 0;
    }
    g_offsets[NEXP] = s;
}

__global__ void build_kernel() {
    int t = blockIdx.x * blockDim.x + threadIdx.x;
    if (t >= NTOK) return;
#pragma unroll
    for (int k = 0; k < TOPK; k++) {
        int e = g_tok_eidx[t * 2 + k];
        int pos = g_offsets[e] + atomicAdd(&g_fill[e], 1);
        g_rows_token[pos] = t;
        g_rows_dest[pos] = t * 2 + k;
    }
}

// ---------------- fp32 -> fp16 splits; dest selected IN-BODY --------------------
// W=0: x -> g_xhi/g_xlo (hi+lo) ; W=1: w1 -> g_w1h (hi only) ; W=2: w2 -> g_w2h
template <int W>
__global__ void split_kernel(const float* __restrict__ src) {
    size_t i = (size_t)blockIdx.x * blockDim.x + threadIdx.x;   // 4 elems each
    float4 v = reinterpret_cast<const float4*>(src)[i];
    if (W == 0) {
        __half2 h0, l0, h1, l1;
        split2h(v.x, v.y, h0, l0);
        split2h(v.z, v.w, h1, l1);
        reinterpret_cast<__half2*>(g_xhi)[2 * i]     = h0;
        reinterpret_cast<__half2*>(g_xhi)[2 * i + 1] = h1;
        reinterpret_cast<__half2*>(g_xlo)[2 * i]     = l0;
        reinterpret_cast<__half2*>(g_xlo)[2 * i + 1] = l1;
    } else {
        __half* dh = (W == 1) ? g_w1h : g_w2h;
        reinterpret_cast<__half2*>(dh)[2 * i]     = __floats2half2_rn(v.x, v.y);
        reinterpret_cast<__half2*>(dh)[2 * i + 1] = __floats2half2_rn(v.z, v.w);
    }
}

// ---------------- FAST grouped GEMM: fp16 2-pass, 4-stage, 1 barrier/chunk (R14) -
// MODE 1: A = x hi/lo (gathered), B = w1h [K=D][N=H], +b1, GELU -> g_h hi/lo
// MODE 2: A = g_h hi/lo (contig), B = w2h [K=H][N=D], +b2 -> g_oscr[slot]
template <int MODE>
__global__ __launch_bounds__(256, 2)
void moe_gemm_wmma(const float* __restrict__ bias) {
    constexpr int KDIM = (MODE == 1) ? DDIM : HDIM;
    constexpr int NDIM = (MODE == 1) ? HDIM : DDIM;
    constexpr int NCH = KDIM / KC;

    extern __shared__ __align__(16) __half sm[];

    int e = blockIdx.z;
    int roff = g_offsets[e];
    int cnt = g_offsets[e + 1] - roff;
    int m0 = blockIdx.y * TM;
    if (m0 >= cnt) return;
    int n0 = blockIdx.x * TN;

    int tid = threadIdx.x;
    int wid = tid >> 5, lane = tid & 31;
    int wm = wid & 1;            // m block: wm*64 (4 frags)
    int wn = wid >> 1;           // n block: wn*32 (2 frags)

    const __half* Ahi = (MODE == 1) ? g_xhi : g_hhi;
    const __half* Alo = (MODE == 1) ? g_xlo : g_hlo;
    const __half* Bh  = ((MODE == 1) ? g_w1h : g_w2h) + (size_t)e * KDIM * NDIM;

    // --- cp.async staging geometry -----------------------------------------------
    int arow = tid >> 1;
    int akc = (tid & 1) * 8;
    int src;
    if (MODE == 1) {
        src = (m0 + arow < cnt) ? g_rows_token[roff + m0 + arow] : 0;
    } else {
        int g = roff + m0 + arow;
        src = (g < NROWS) ? g : (NROWS - 1);
    }
    size_t aofs = (size_t)src * KDIM + akc;
    uint32_t a_dst = (uint32_t)(arow * A_PAD + akc) * 2;
    int bkr = tid >> 4;
    int bnc = (tid & 15) * 8;
    size_t bofs = (size_t)bkr * NDIM + n0 + bnc;
    uint32_t b_dst = (uint32_t)(bkr * B_PAD + bnc) * 2;

    uint32_t smb = smem_u32(sm);

    auto load_stage = [&](int c) {
        uint32_t sb = smb + (uint32_t)(c % NSTG) * (STG_ELS * 2);
        size_t k0 = (size_t)c * KC;
        cpasync16(sb + a_dst,                 Ahi + aofs + k0);
        cpasync16(sb + A_ELS * 2 + a_dst,     Alo + aofs + k0);
        cpasync16(sb + 2 * A_ELS * 2 + b_dst, Bh + bofs + k0 * NDIM);
        cp_commit();
    };

    wmma::fragment<wmma::accumulator, 16, 16, 16, float> acc[4][2];
#pragma unroll
    for (int mf = 0; mf < 4; mf++)
#pragma unroll
        for (int nf = 0; nf < 2; nf++)
            wmma::fill_fragment(acc[mf][nf], 0.0f);

    // prologue: NSTG-1 stages in flight
    load_stage(0);
    load_stage(1);
    load_stage(2);

    for (int c = 0; c < NCH; c++) {
        int rem = NCH - 1 - c;
        if (rem >= 2) cp_wait2();
        else if (rem == 1) cp_wait1();
        else cp_wait0();
        __syncthreads();   // visibility of stage c + WAR retire of compute(c-1)

        const __half* base = sm + (c % NSTG) * STG_ELS;
        const __half* pAh = base;
        const __half* pAl = base + A_ELS;
        const __half* pBh = base + 2 * A_ELS;

        wmma::fragment<wmma::matrix_b, 16, 16, 16, __half, wmma::row_major> bH[2];
#pragma unroll
        for (int nf = 0; nf < 2; nf++)
            wmma::load_matrix_sync(bH[nf], pBh + wn * 32 + nf * 16, B_PAD);
#pragma unroll
        for (int mf = 0; mf < 4; mf++) {
            wmma::fragment<wmma::matrix_a, 16, 16, 16, __half, wmma::row_major> aH, aL;
            const __half* aa = pAh + (wm * 64 + mf * 16) * A_PAD;
            wmma::load_matrix_sync(aH, aa, A_PAD);
            wmma::load_matrix_sync(aL, aa + A_ELS, A_PAD);
#pragma unroll
            for (int nf = 0; nf < 2; nf++) {
                wmma::mma_sync(acc[mf][nf], aH, bH[nf], acc[mf][nf]);
                wmma::mma_sync(acc[mf][nf], aL, bH[nf], acc[mf][nf]);
            }
        }

        // load AFTER compute (R14-proven ordering; R16 early-issue falsified)
        if (c + 3 < NCH) load_stage(c + 3);
    }

    // --- epilogue: per-warp smem scratch ------------------------------------------
    __syncthreads();
    float* scr = reinterpret_cast<float*>(sm) + wid * 16 * 20;   // 16x16 tile, ldm=20
    const float* be = bias + (size_t)e * NDIM;
    int lrow = lane >> 1;
    int lcol = (lane & 1) * 8;
#pragma unroll
    for (int mf = 0; mf < 4; mf++) {
#pragma unroll
        for (int nf = 0; nf < 2; nf++) {
            wmma::store_matrix_sync(scr, acc[mf][nf], 20, wmma::mem_row_major);
            __syncwarp();
            int r = m0 + wm * 64 + mf * 16 + lrow;
            if (r < cnt) {
                int col = n0 + wn * 32 + nf * 16 + lcol;
                if (MODE == 1) {
                    size_t drow = (size_t)(roff + r) * NDIM;
#pragma unroll
                    for (int j = 0; j < 8; j += 2) {
                        float v0 = gelu_exact(scr[lrow * 20 + lcol + j]     + be[col + j]);
                        float v1 = gelu_exact(scr[lrow * 20 + lcol + j + 1] + be[col + j + 1]);
                        __half2 h2, l2;
                        split2h(v0, v1, h2, l2);
                        *reinterpret_cast<__half2*>(g_hhi + drow + col + j) = h2;
                        *reinterpret_cast<__half2*>(g_hlo + drow + col + j) = l2;
                    }
                } else {
                    size_t drow = (size_t)g_rows_dest[roff + r] * NDIM;
                    float out[8];
#pragma unroll
                    for (int j = 0; j < 8; j++)
                        out[j] = scr[lrow * 20 + lcol + j] + be[col + j];
                    float* dst = g_oscr + drow + col;
                    *reinterpret_cast<float4*>(dst)     = make_float4(out[0], out[1], out[2], out[3]);
                    *reinterpret_cast<float4*>(dst + 4) = make_float4(out[4], out[5], out[6], out[7]);
                }
            }
            __syncwarp();
        }
    }
}

// ---------------- check kernels: dead (all-zero) AND NaN detection ----------------
__global__ void check_h_kernel() {
    size_t idx = ((size_t)blockIdx.x * blockDim.x + threadIdx.x) * 1024;
    if (idx < (size_t)NROWS * HDIM) {
        unsigned short u = __half_as_ushort(g_hhi[idx]);
        if (u != 0) g_flag1 = 0;
        if ((u & 0x7C00) == 0x7C00 && (u & 0x03FF) != 0) g_nan1 = 1;   // fp16 NaN
    }
}
__global__ void check_o_kernel() {
    size_t idx = ((size_t)blockIdx.x * blockDim.x + threadIdx.x) * 1024;
    if (idx < (size_t)NROWS * DDIM) {
        float v = g_oscr[idx];
        if (v != 0.0f) g_flag2 = 0;
        if (isnan(v) || isinf(v)) g_nan2 = 1;
    }
}

// ---------------- FALLBACK SIMT GEMMs (proven; statics in-body) ------------------
template <int MODE>
__global__ __launch_bounds__(256)
void fb_gemm(const float* __restrict__ Aparam,
             const float* __restrict__ Bmat,
             const float* __restrict__ bias) {
    if (MODE == 1) { if (g_flag1 == 0 && g_nan1 == 0) return; }
    else           { if (g_flag2 == 0 && g_nan2 == 0) return; }

    constexpr int KDIM = (MODE == 1) ? DDIM : HDIM;
    constexpr int NDIM = (MODE == 1) ? HDIM : DDIM;

    int e = blockIdx.z;
    int roff = g_offsets[e];
    int cnt = g_offsets[e + 1] - roff;
    int m0 = blockIdx.y * FBM;
    if (m0 >= cnt) return;
    int n0 = blockIdx.x * FBN;

    const float* Bexp = Bmat + (size_t)e * KDIM * NDIM;
    const float* bexp = bias + (size_t)e * NDIM;

    __shared__ float As[FBK][FBM];
    __shared__ float Bs[FBK][FBN];
    __shared__ int rowsrc[FBM];

    int tid = threadIdx.x;
    if (tid < FBM) {
        int r = m0 + tid;
        int src = -1;
        if (r < cnt) src = (MODE == 1) ? g_rows_token[roff + r] : (roff + r);
        rowsrc[tid] = src;
    }
    __syncthreads();

    float acc[8][8];
#pragma unroll
    for (int i = 0; i < 8; i++)
#pragma unroll
        for (int j = 0; j < 8; j++) acc[i][j] = 0.f;

    int ty = tid >> 4, tx = tid & 15;

    for (int k0 = 0; k0 < KDIM; k0 += FBK) {
#pragma unroll
        for (int p = 0; p < 2; p++) {
            int row = (tid >> 2) + p * 64;
            int c4 = (tid & 3) * 4;
            int src = rowsrc[row];
            float f0 = 0.f, f1 = 0.f, f2 = 0.f, f3 = 0.f;
            if (src >= 0) {
                if (MODE == 1) {
                    float4 v = *reinterpret_cast<const float4*>(
                        Aparam + (size_t)src * KDIM + k0 + c4);
                    f0 = v.x; f1 = v.y; f2 = v.z; f3 = v.w;
                } else {
                    __half2 vh0 = *reinterpret_cast<const __half2*>(g_hhi + (size_t)src * KDIM + k0 + c4);
                    __half2 vh1 = *reinterpret_cast<const __half2*>(g_hhi + (size_t)src * KDIM + k0 + c4 + 2);
                    __half2 vl0 = *reinterpret_cast<const __half2*>(g_hlo + (size_t)src * KDIM + k0 + c4);
                    __half2 vl1 = *reinterpret_cast<const __half2*>(g_hlo + (size_t)src * KDIM + k0 + c4 + 2);
                    f0 = __half2float(__low2half(vh0))  + __half2float(__low2half(vl0));
                    f1 = __half2float(__high2half(vh0)) + __half2float(__high2half(vl0));
                    f2 = __half2float(__low2half(vh1))  + __half2float(__low2half(vl1));
                    f3 = __half2float(__high2half(vh1)) + __half2float(__high2half(vl1));
                }
            }
            As[c4 + 0][row] = f0;
            As[c4 + 1][row] = f1;
            As[c4 + 2][row] = f2;
            As[c4 + 3][row] = f3;
        }
#pragma unroll
        for (int p = 0; p < 2; p++) {
            int brow2 = (tid >> 5) + p * 8;
            int bc = (tid & 31) * 4;
            float4 v = *reinterpret_cast<const float4*>(
                Bexp + (size_t)(k0 + brow2) * NDIM + n0 + bc);
            *reinterpret_cast<float4*>(&Bs[brow2][bc]) = v;
        }
        __syncthreads();

#pragma unroll
        for (int kk = 0; kk < FBK; kk++) {
            float a[8], b[8];
#pragma unroll
            for (int i = 0; i < 8; i++) a[i] = As[kk][ty * 8 + i];
#pragma unroll
            for (int j = 0; j < 8; j++) b[j] = Bs[kk][tx * 8 + j];
#pragma unroll
            for (int i = 0; i < 8; i++)
#pragma unroll
                for (int j = 0; j < 8; j++)
                    acc[i][j] = fmaf(a[i], b[j], acc[i][j]);
        }
        __syncthreads();
    }

#pragma unroll
    for (int i = 0; i < 8; i++) {
        int r = m0 + ty * 8 + i;
        if (r >= cnt) continue;
#pragma unroll
        for (int j = 0; j < 8; j++) {
            int col = n0 + tx * 8 + j;
            float v = acc[i][j] + bexp[col];
            if (MODE == 1) {
                v = gelu_exact(v);
                __half h = __float2half(v);
                __half l = __float2half(v - __half2float(h));
                size_t o = (size_t)(roff + r) * NDIM + col;
                g_hhi[o] = h;
                g_hlo[o] = l;
            } else {
                int slot = g_rows_dest[roff + r];
                g_oscr[(size_t)slot * NDIM + col] = v;
            }
        }
    }
}

// ---------------- combine ------------------------------------------------------
__global__ void combine_kernel(float* __restrict__ y) {
    int idx = blockIdx.x * blockDim.x + threadIdx.x;
    if (idx >= NTOK * DDIM) return;
    int t = idx >> 10;
    int d = idx & (DDIM - 1);
    float w0 = g_wslot[t * 2 + 0];
    float w1 = g_wslot[t * 2 + 1];
    float v0 = g_oscr[(size_t)(t * 2 + 0) * DDIM + d];
    float v1 = g_oscr[(size_t)(t * 2 + 1) * DDIM + d];
    y[idx] = fmaf(w0, v0, w1 * v1);
}

// ---------------- launch (NO device symbols passed as kernel arguments) ---------
extern "C" void kernel_launch(void* const* d_in, const int* in_sizes, int n_in,
                              void* d_out, int out_size) {
    const float* x  = (const float*)d_in[0];  // [B,S,D]
    const float* gw = (const float*)d_in[1];  // [D,E]
    const float* w1 = (const float*)d_in[2];  // [E,D,H]
    const float* b1 = (const float*)d_in[3];  // [E,H]
    const float* w2 = (const float*)d_in[4];  // [E,H,D]
    const float* b2 = (const float*)d_in[5];  // [E,D]
    float* y = (float*)d_out;

    // dynamic smem opt-in (host attribute; capture-safe, proven)
    cudaFuncSetAttribute(moe_gemm_wmma<1>, cudaFuncAttributeMaxDynamicSharedMemorySize, SMEM_DYN);
    cudaFuncSetAttribute(moe_gemm_wmma<2>, cudaFuncAttributeMaxDynamicSharedMemorySize, SMEM_DYN);

    reset_kernel<<<1, 32>>>();
    gate_kernel<<<NTOK / 8, 256>>>(x, gw);
    scan_kernel<<<1, 1>>>();
    build_kernel<<<NTOK / 256, 256>>>();

    // convert-once fp16 splits (dest statics selected in-body)
    split_kernel<0><<<(NTOK * DDIM / 4) / 256, 256>>>(x);
    split_kernel<1><<<((size_t)NEXP * DDIM * HDIM / 4) / 256, 256>>>(w1);
    split_kernel<2><<<((size_t)NEXP * HDIM * DDIM / 4) / 256, 256>>>(w2);

    // fast GEMM1 (wmma fp16 2-pass) + self-check + fallback
    moe_gemm_wmma<1><<<dim3(HDIM / TN, NROWS / TM, NEXP), 256, SMEM_DYN>>>(b1);
    check_h_kernel<<<256, 256>>>();
    fb_gemm<1><<<dim3(HDIM / FBN, NROWS / FBM, NEXP), 256>>>(x, w1, b1);

    // fast GEMM2 + self-check + fallback
    moe_gemm_wmma<2><<<dim3(DDIM / TN, NROWS / TM, NEXP), 256, SMEM_DYN>>>(b2);
    check_o_kernel<<<64, 256>>>();
    fb_gemm<2><<<dim3(DDIM / FBN, NROWS / FBM, NEXP), 256>>>(nullptr, w2, b2);

    combine_kernel<<<(NTOK * DDIM) / 256, 256>>>(y);
}